// round 6
// baseline (speedup 1.0000x reference)
#include <cuda_runtime.h>
#include <cuda_bf16.h>
#include <cstdint>

#define N_NODES 50000
#define CH      256
#define N_EDGES 800000
#define NSCAN   196          // ceil(50000/256)

// ---------------- scratch (device globals) ------------------------------------
__device__ __nv_bfloat16 g_xwb[N_NODES * CH];  // x @ conv_w, bf16 (25.6 MB)
__device__ float g_dinv[N_NODES];
__device__ int   g_sdeg[N_NODES];
__device__ int   g_cnt [N_NODES];
__device__ int   g_rowptr[N_NODES];
__device__ int   g_cursor[N_NODES];
__device__ int   g_bsum[NSCAN];
__device__ int   g_csr_src [N_EDGES];
__device__ float g_csr_coef[N_EDGES];
__device__ float g_s[CH];

// ---------------- init ---------------------------------------------------------
__global__ void k_init0() {
    int i = blockIdx.x * blockDim.x + threadIdx.x;
    if (i < N_NODES) { g_sdeg[i] = 1; g_cnt[i] = 0; }
    if (i < CH)      g_s[i] = 0.0f;
}

// ---------------- histograms -----------------------------------------------------
__global__ void k_count(const int* __restrict__ src, const int* __restrict__ dst) {
    int e = blockIdx.x * blockDim.x + threadIdx.x;
    if (e < N_EDGES) {
        atomicAdd(&g_sdeg[src[e]], 1);
        atomicAdd(&g_cnt[dst[e]], 1);
    }
}

__global__ void k_dinv() {
    int i = blockIdx.x * blockDim.x + threadIdx.x;
    if (i < N_NODES) g_dinv[i] = rsqrtf((float)g_sdeg[i]);
}

// ---------------- 3-kernel exclusive scan over g_cnt ----------------------------
__global__ void k_scan1() {
    __shared__ int sh[256];
    int t = threadIdx.x, i = blockIdx.x * 256 + t;
    int v = (i < N_NODES) ? g_cnt[i] : 0;
    sh[t] = v; __syncthreads();
    #pragma unroll
    for (int off = 1; off < 256; off <<= 1) {
        int add = (t >= off) ? sh[t - off] : 0;
        __syncthreads();
        sh[t] += add;
        __syncthreads();
    }
    if (i < N_NODES) g_rowptr[i] = sh[t] - v;
    if (t == 255) g_bsum[blockIdx.x] = sh[255];
}

__global__ void k_scan2() {
    __shared__ int sh[256];
    int t = threadIdx.x;
    int v = (t < NSCAN) ? g_bsum[t] : 0;
    sh[t] = v; __syncthreads();
    #pragma unroll
    for (int off = 1; off < 256; off <<= 1) {
        int add = (t >= off) ? sh[t - off] : 0;
        __syncthreads();
        sh[t] += add;
        __syncthreads();
    }
    if (t < NSCAN) g_bsum[t] = sh[t] - v;
}

__global__ void k_scan3() {
    int i = blockIdx.x * blockDim.x + threadIdx.x;
    if (i < N_NODES) {
        int r = g_rowptr[i] + g_bsum[i >> 8];
        g_rowptr[i] = r;
        g_cursor[i] = r;
    }
}

// ---------------- CSR fill --------------------------------------------------------
__global__ void k_fill(const int* __restrict__ src, const int* __restrict__ dst) {
    int e = blockIdx.x * blockDim.x + threadIdx.x;
    if (e < N_EDGES) {
        int s = src[e], d = dst[e];
        int pos = atomicAdd(&g_cursor[d], 1);
        g_csr_src[pos]  = s;
        g_csr_coef[pos] = g_dinv[s] * g_dinv[d];
    }
}

// =================================================================================
// Split-bf16 tensor-core GEMM via mma.sync (unchanged from R5 except bf16 epilogue)
// =================================================================================
#define TB_M 128
#define TB_N 128
#define TB_K 32
#define APAD 40

__device__ __forceinline__ void mma16816(float* c, const uint32_t* a, const uint32_t* b) {
    asm volatile(
        "mma.sync.aligned.m16n8k16.row.col.f32.bf16.bf16.f32 "
        "{%0,%1,%2,%3}, {%4,%5,%6,%7}, {%8,%9}, {%0,%1,%2,%3};"
        : "+f"(c[0]), "+f"(c[1]), "+f"(c[2]), "+f"(c[3])
        : "r"(a[0]), "r"(a[1]), "r"(a[2]), "r"(a[3]), "r"(b[0]), "r"(b[1]));
}

__global__ void __launch_bounds__(256) k_gemm_mma(const float* __restrict__ X,
                                                  const float* __restrict__ W) {
    __shared__ __nv_bfloat16 Ahi[TB_M][APAD];
    __shared__ __nv_bfloat16 Alo[TB_M][APAD];
    __shared__ __nv_bfloat16 Bhi[TB_N][APAD];
    __shared__ __nv_bfloat16 Blo[TB_N][APAD];

    const int tid  = threadIdx.x;
    const int wid  = tid >> 5;
    const int lane = tid & 31;
    const int wm   = wid >> 1;
    const int wn   = wid & 1;
    const int bm   = blockIdx.x * TB_M;
    const int n0   = blockIdx.y * TB_N;

    const int qr = lane >> 2;
    const int qc = (lane & 3) << 1;

    float acc[2][8][4];
    #pragma unroll
    for (int mi = 0; mi < 2; mi++)
        #pragma unroll
        for (int ni = 0; ni < 8; ni++)
            #pragma unroll
            for (int j = 0; j < 4; j++) acc[mi][ni][j] = 0.f;

    for (int k0 = 0; k0 < CH; k0 += TB_K) {
        #pragma unroll
        for (int i = tid; i < TB_M * (TB_K / 4); i += 256) {
            int row = i >> 3;
            int c4  = (i & 7) << 2;
            float4 v = make_float4(0.f, 0.f, 0.f, 0.f);
            int gr = bm + row;
            if (gr < N_NODES) v = *(const float4*)&X[gr * CH + k0 + c4];
            #pragma unroll
            for (int j = 0; j < 4; j++) {
                float f = (j == 0) ? v.x : (j == 1) ? v.y : (j == 2) ? v.z : v.w;
                __nv_bfloat16 h = __float2bfloat16_rn(f);
                Ahi[row][c4 + j] = h;
                Alo[row][c4 + j] = __float2bfloat16_rn(f - __bfloat162float(h));
            }
        }
        #pragma unroll
        for (int i = tid; i < TB_K * (TB_N / 4); i += 256) {
            int k  = i >> 5;
            int n4 = (i & 31) << 2;
            float4 v = *(const float4*)&W[(k0 + k) * CH + n0 + n4];
            #pragma unroll
            for (int j = 0; j < 4; j++) {
                float f = (j == 0) ? v.x : (j == 1) ? v.y : (j == 2) ? v.z : v.w;
                __nv_bfloat16 h = __float2bfloat16_rn(f);
                Bhi[n4 + j][k] = h;
                Blo[n4 + j][k] = __float2bfloat16_rn(f - __bfloat162float(h));
            }
        }
        __syncthreads();

        #pragma unroll
        for (int ks = 0; ks < 2; ks++) {
            const int kk = ks * 16;
            uint32_t ah[2][4], al[2][4];
            #pragma unroll
            for (int mi = 0; mi < 2; mi++) {
                int r0 = wm * 32 + mi * 16;
                ah[mi][0] = *(const uint32_t*)&Ahi[r0 + qr][kk + qc];
                ah[mi][1] = *(const uint32_t*)&Ahi[r0 + qr + 8][kk + qc];
                ah[mi][2] = *(const uint32_t*)&Ahi[r0 + qr][kk + qc + 8];
                ah[mi][3] = *(const uint32_t*)&Ahi[r0 + qr + 8][kk + qc + 8];
                al[mi][0] = *(const uint32_t*)&Alo[r0 + qr][kk + qc];
                al[mi][1] = *(const uint32_t*)&Alo[r0 + qr + 8][kk + qc];
                al[mi][2] = *(const uint32_t*)&Alo[r0 + qr][kk + qc + 8];
                al[mi][3] = *(const uint32_t*)&Alo[r0 + qr + 8][kk + qc + 8];
            }
            uint32_t bh[8][2], bl[8][2];
            #pragma unroll
            for (int ni = 0; ni < 8; ni++) {
                int n = wn * 64 + ni * 8 + qr;
                bh[ni][0] = *(const uint32_t*)&Bhi[n][kk + qc];
                bh[ni][1] = *(const uint32_t*)&Bhi[n][kk + qc + 8];
                bl[ni][0] = *(const uint32_t*)&Blo[n][kk + qc];
                bl[ni][1] = *(const uint32_t*)&Blo[n][kk + qc + 8];
            }
            #pragma unroll
            for (int mi = 0; mi < 2; mi++)
                #pragma unroll
                for (int ni = 0; ni < 8; ni++) {
                    mma16816(acc[mi][ni], ah[mi], bh[ni]);
                    mma16816(acc[mi][ni], ah[mi], bl[ni]);
                    mma16816(acc[mi][ni], al[mi], bh[ni]);
                }
        }
        __syncthreads();
    }

    // ---- epilogue: bf16 stores ----
    #pragma unroll
    for (int mi = 0; mi < 2; mi++) {
        int r0 = bm + wm * 32 + mi * 16 + qr;
        #pragma unroll
        for (int ni = 0; ni < 8; ni++) {
            int cg = n0 + wn * 64 + ni * 8 + qc;
            if (r0 < N_NODES) {
                __nv_bfloat162 p;
                p.x = __float2bfloat16_rn(acc[mi][ni][0]);
                p.y = __float2bfloat16_rn(acc[mi][ni][1]);
                *(__nv_bfloat162*)&g_xwb[r0 * CH + cg] = p;
            }
            if (r0 + 8 < N_NODES) {
                __nv_bfloat162 p;
                p.x = __float2bfloat16_rn(acc[mi][ni][2]);
                p.y = __float2bfloat16_rn(acc[mi][ni][3]);
                *(__nv_bfloat162*)&g_xwb[(r0 + 8) * CH + cg] = p;
            }
        }
    }
}

// ---------------- fused gather + self-loop + relu + node-sum ---------------------
// One warp per node; lane owns 8 bf16 channels (one uint4). 8-edge shfl batching.
#define GATHER_BLOCKS 1184
__global__ void __launch_bounds__(256) k_gather(const float* __restrict__ conv_b) {
    const int lane = threadIdx.x & 31;
    const int warp = (blockIdx.x * blockDim.x + threadIdx.x) >> 5;
    const int nwarps = (GATHER_BLOCKS * 256) >> 5;
    const int c = lane << 3;                       // 8 channels per lane

    const float4 b0 = *(const float4*)&conv_b[c];
    const float4 b1 = *(const float4*)&conv_b[c + 4];
    float hs[8] = {0.f,0.f,0.f,0.f,0.f,0.f,0.f,0.f};

    for (int n = warp; n < N_NODES; n += nwarps) {
        float a[8] = {0.f,0.f,0.f,0.f,0.f,0.f,0.f,0.f};
        const int beg = g_rowptr[n];
        const int cnt = g_cnt[n];

        int k = 0;
        for (; k + 8 <= cnt; k += 8) {
            int   s_l  = 0;
            float cf_l = 0.f;
            if (lane < 8) {
                s_l  = g_csr_src [beg + k + lane];
                cf_l = g_csr_coef[beg + k + lane];
            }
            #pragma unroll
            for (int j = 0; j < 8; j++) {
                int   s  = __shfl_sync(0xffffffff, s_l,  j);
                float cf = __shfl_sync(0xffffffff, cf_l, j);
                uint4 v = *(const uint4*)&g_xwb[s * CH + c];
                a[0] += cf * __uint_as_float(v.x << 16);
                a[1] += cf * __uint_as_float(v.x & 0xffff0000u);
                a[2] += cf * __uint_as_float(v.y << 16);
                a[3] += cf * __uint_as_float(v.y & 0xffff0000u);
                a[4] += cf * __uint_as_float(v.z << 16);
                a[5] += cf * __uint_as_float(v.z & 0xffff0000u);
                a[6] += cf * __uint_as_float(v.w << 16);
                a[7] += cf * __uint_as_float(v.w & 0xffff0000u);
            }
        }
        if (k < cnt) {
            int rem = cnt - k;
            int   s_l  = 0;
            float cf_l = 0.f;
            if (lane < rem) {
                s_l  = g_csr_src [beg + k + lane];
                cf_l = g_csr_coef[beg + k + lane];
            }
            for (int j = 0; j < rem; j++) {
                int   s  = __shfl_sync(0xffffffff, s_l,  j);
                float cf = __shfl_sync(0xffffffff, cf_l, j);
                uint4 v = *(const uint4*)&g_xwb[s * CH + c];
                a[0] += cf * __uint_as_float(v.x << 16);
                a[1] += cf * __uint_as_float(v.x & 0xffff0000u);
                a[2] += cf * __uint_as_float(v.y << 16);
                a[3] += cf * __uint_as_float(v.y & 0xffff0000u);
                a[4] += cf * __uint_as_float(v.z << 16);
                a[5] += cf * __uint_as_float(v.z & 0xffff0000u);
                a[6] += cf * __uint_as_float(v.w << 16);
                a[7] += cf * __uint_as_float(v.w & 0xffff0000u);
            }
        }
        {   // self loop
            float dn = g_dinv[n];
            float c2 = dn * dn;
            uint4 v = *(const uint4*)&g_xwb[n * CH + c];
            a[0] += c2 * __uint_as_float(v.x << 16);
            a[1] += c2 * __uint_as_float(v.x & 0xffff0000u);
            a[2] += c2 * __uint_as_float(v.y << 16);
            a[3] += c2 * __uint_as_float(v.y & 0xffff0000u);
            a[4] += c2 * __uint_as_float(v.z << 16);
            a[5] += c2 * __uint_as_float(v.z & 0xffff0000u);
            a[6] += c2 * __uint_as_float(v.w << 16);
            a[7] += c2 * __uint_as_float(v.w & 0xffff0000u);
        }
        hs[0] += fmaxf(a[0] + b0.x, 0.f);
        hs[1] += fmaxf(a[1] + b0.y, 0.f);
        hs[2] += fmaxf(a[2] + b0.z, 0.f);
        hs[3] += fmaxf(a[3] + b0.w, 0.f);
        hs[4] += fmaxf(a[4] + b1.x, 0.f);
        hs[5] += fmaxf(a[5] + b1.y, 0.f);
        hs[6] += fmaxf(a[6] + b1.z, 0.f);
        hs[7] += fmaxf(a[7] + b1.w, 0.f);
    }
    #pragma unroll
    for (int i = 0; i < 8; i++) atomicAdd(&g_s[c + i], hs[i]);
}

// ---------------- 4 tanh GEMVs -----------------------------------------------------
__global__ void k_gemv(const float* __restrict__ fc1w, const float* __restrict__ fc1b,
                       const float* __restrict__ fc2w, const float* __restrict__ fc2b,
                       const float* __restrict__ fc3w, const float* __restrict__ fc3b,
                       const float* __restrict__ fc4w, const float* __restrict__ fc4b,
                       float* __restrict__ out) {
    __shared__ float ss[CH];
    const int t = threadIdx.x;
    if (t < CH) ss[t] = g_s[t];
    __syncthreads();

    const float* w; const float* bb; int row;
    if (t < 256)      { w = fc1w; bb = fc1b; row = t; }
    else if (t < 512) { w = fc2w; bb = fc2b; row = t - 256; }
    else if (t < 640) { w = fc3w; bb = fc3b; row = t - 512; }
    else              { w = fc4w; bb = fc4b; row = t - 640; }

    float acc = bb[row];
    const float4* wr = (const float4*)(w + row * CH);
    #pragma unroll
    for (int k = 0; k < CH / 4; k++) {
        float4 wv = wr[k];
        acc += ss[4 * k + 0] * wv.x + ss[4 * k + 1] * wv.y +
               ss[4 * k + 2] * wv.z + ss[4 * k + 3] * wv.w;
    }
    out[t] = tanhf(acc);
}

// ---------------- launch -------------------------------------------------------------
extern "C" void kernel_launch(void* const* d_in, const int* in_sizes, int n_in,
                              void* d_out, int out_size) {
    const float* x      = (const float*)d_in[0];
    const int*   ei     = (const int*)  d_in[1];
    const float* conv_w = (const float*)d_in[2];
    const float* conv_b = (const float*)d_in[3];
    const float* fc1w   = (const float*)d_in[4];
    const float* fc1b   = (const float*)d_in[5];
    const float* fc2w   = (const float*)d_in[6];
    const float* fc2b   = (const float*)d_in[7];
    const float* fc3w   = (const float*)d_in[8];
    const float* fc3b   = (const float*)d_in[9];
    const float* fc4w   = (const float*)d_in[10];
    const float* fc4b   = (const float*)d_in[11];
    float* out = (float*)d_out;

    const int* src = ei;
    const int* dst = ei + N_EDGES;

    k_init0<<<NSCAN, 256>>>();
    k_count<<<(N_EDGES + 255) / 256, 256>>>(src, dst);
    k_dinv<<<NSCAN, 256>>>();
    k_scan1<<<NSCAN, 256>>>();
    k_scan2<<<1, 256>>>();
    k_scan3<<<NSCAN, 256>>>();
    k_fill<<<(N_EDGES + 255) / 256, 256>>>(src, dst);

    dim3 gg((N_NODES + TB_M - 1) / TB_M, CH / TB_N);
    k_gemm_mma<<<gg, 256>>>(x, conv_w);

    k_gather<<<GATHER_BLOCKS, 256>>>(conv_b);

    k_gemv<<<1, 768>>>(fc1w, fc1b, fc2w, fc2b, fc3w, fc3b, fc4w, fc4b, out);
}

// round 7
// speedup vs baseline: 2.1426x; 2.1426x over previous
#include <cuda_runtime.h>
#include <cuda_bf16.h>
#include <cstdint>

#define N_NODES 50000
#define CH      256
#define N_EDGES 800000
#define NSCAN   196          // ceil(50000/256)

// ---------------- scratch (device globals) ------------------------------------
__device__ float g_xw  [N_NODES * CH];   // x @ conv_w fp32 (51.2 MB)
__device__ __nv_bfloat16 g_whi[CH * CH]; // W^T hi, [n][k]
__device__ __nv_bfloat16 g_wlo[CH * CH]; // W^T lo, [n][k]
__device__ float g_dinv[N_NODES];
__device__ int   g_sdeg[N_NODES];
__device__ int   g_cnt [N_NODES];
__device__ int   g_rowptr[N_NODES];
__device__ int   g_cursor[N_NODES];
__device__ int   g_bsum[NSCAN];
__device__ int2  g_csr[N_EDGES];         // {src, coef-as-int}
__device__ float g_s[CH];

// ---------------- init ---------------------------------------------------------
__global__ void k_init0() {
    int i = blockIdx.x * blockDim.x + threadIdx.x;
    if (i < N_NODES) { g_sdeg[i] = 1; g_cnt[i] = 0; }
    if (i < CH)      g_s[i] = 0.0f;
}

// ---------------- histograms -----------------------------------------------------
__global__ void k_count(const int* __restrict__ src, const int* __restrict__ dst) {
    int e = blockIdx.x * blockDim.x + threadIdx.x;
    if (e < N_EDGES) {
        atomicAdd(&g_sdeg[src[e]], 1);
        atomicAdd(&g_cnt[dst[e]], 1);
    }
}

// ---------------- W split/transpose: g_whi/g_wlo[n][k] ---------------------------
__global__ void k_splitW(const float* __restrict__ W) {
    int i = blockIdx.x * blockDim.x + threadIdx.x;   // 0..65535
    int k = i >> 8, n = i & 255;
    float f = W[i];                                   // W[k][n]
    __nv_bfloat16 h = __float2bfloat16_rn(f);
    g_whi[n * CH + k] = h;
    g_wlo[n * CH + k] = __float2bfloat16_rn(f - __bfloat162float(h));
}

__global__ void k_dinv() {
    int i = blockIdx.x * blockDim.x + threadIdx.x;
    if (i < N_NODES) g_dinv[i] = rsqrtf((float)g_sdeg[i]);
}

// ---------------- 3-kernel exclusive scan over g_cnt ----------------------------
__global__ void k_scan1() {
    __shared__ int sh[256];
    int t = threadIdx.x, i = blockIdx.x * 256 + t;
    int v = (i < N_NODES) ? g_cnt[i] : 0;
    sh[t] = v; __syncthreads();
    #pragma unroll
    for (int off = 1; off < 256; off <<= 1) {
        int add = (t >= off) ? sh[t - off] : 0;
        __syncthreads();
        sh[t] += add;
        __syncthreads();
    }
    if (i < N_NODES) g_rowptr[i] = sh[t] - v;
    if (t == 255) g_bsum[blockIdx.x] = sh[255];
}

__global__ void k_scan2() {
    __shared__ int sh[256];
    int t = threadIdx.x;
    int v = (t < NSCAN) ? g_bsum[t] : 0;
    sh[t] = v; __syncthreads();
    #pragma unroll
    for (int off = 1; off < 256; off <<= 1) {
        int add = (t >= off) ? sh[t - off] : 0;
        __syncthreads();
        sh[t] += add;
        __syncthreads();
    }
    if (t < NSCAN) g_bsum[t] = sh[t] - v;
}

__global__ void k_scan3() {
    int i = blockIdx.x * blockDim.x + threadIdx.x;
    if (i < N_NODES) {
        int r = g_rowptr[i] + g_bsum[i >> 8];
        g_rowptr[i] = r;
        g_cursor[i] = r;
    }
}

// ---------------- CSR fill (packed int2 metadata) --------------------------------
__global__ void k_fill(const int* __restrict__ src, const int* __restrict__ dst) {
    int e = blockIdx.x * blockDim.x + threadIdx.x;
    if (e < N_EDGES) {
        int s = src[e], d = dst[e];
        int pos = atomicAdd(&g_cursor[d], 1);
        float cf = g_dinv[s] * g_dinv[d];
        g_csr[pos] = make_int2(s, __float_as_int(cf));
    }
}

// =================================================================================
// Split-bf16 tensor-core GEMM via mma.sync, software-pipelined A staging.
//   g_xw[M,256] = X[M,256] @ W[256,256];  D = Xhi*Whi + Xhi*Wlo + Xlo*Whi
// CTA 128x128, 8 warps 4(M)x2(N), warp 32x64, K chunk 32 (8 chunks).
// W pre-split/transposed to bf16 by k_splitW (L2-hot).
// =================================================================================
#define TB_M 128
#define TB_N 128
#define TB_K 32
#define APAD 40

__device__ __forceinline__ void mma16816(float* c, const uint32_t* a, const uint32_t* b) {
    asm volatile(
        "mma.sync.aligned.m16n8k16.row.col.f32.bf16.bf16.f32 "
        "{%0,%1,%2,%3}, {%4,%5,%6,%7}, {%8,%9}, {%0,%1,%2,%3};"
        : "+f"(c[0]), "+f"(c[1]), "+f"(c[2]), "+f"(c[3])
        : "r"(a[0]), "r"(a[1]), "r"(a[2]), "r"(a[3]), "r"(b[0]), "r"(b[1]));
}

__device__ __forceinline__ uint32_t packbf(float a, float b) {
    __nv_bfloat162 t = __floats2bfloat162_rn(a, b);
    return *(uint32_t*)&t;
}

__global__ void __launch_bounds__(256) k_gemm_mma(const float* __restrict__ X) {
    __shared__ __nv_bfloat16 Ahi[TB_M][APAD];
    __shared__ __nv_bfloat16 Alo[TB_M][APAD];
    __shared__ __nv_bfloat16 Bhi[TB_N][APAD];
    __shared__ __nv_bfloat16 Blo[TB_N][APAD];

    const int tid  = threadIdx.x;
    const int wid  = tid >> 5;
    const int lane = tid & 31;
    const int wm   = wid >> 1;
    const int wn   = wid & 1;
    const int bm   = blockIdx.y * TB_M;          // M index (slow)
    const int n0   = blockIdx.x * TB_N;          // N index (fast) -> X L2 reuse

    const int qr = lane >> 2;
    const int qc = (lane & 3) << 1;

    float acc[2][8][4];
    #pragma unroll
    for (int mi = 0; mi < 2; mi++)
        #pragma unroll
        for (int ni = 0; ni < 8; ni++)
            #pragma unroll
            for (int j = 0; j < 4; j++) acc[mi][ni][j] = 0.f;

    // A staging registers (current chunk's fp32 data)
    float4 stA[4];
    const int a_row = tid >> 3;          // row stride 32 across p
    const int a_c4  = (tid & 7) << 2;

    // prologue: load chunk 0
    #pragma unroll
    for (int p = 0; p < 4; p++) {
        int gr = bm + a_row + p * 32;
        stA[p] = (gr < N_NODES) ? *(const float4*)&X[gr * CH + a_c4]
                                : make_float4(0.f, 0.f, 0.f, 0.f);
    }

    for (int kc = 0; kc < 8; kc++) {
        const int k0 = kc * TB_K;
        // ---- store staged A (split) ----
        #pragma unroll
        for (int p = 0; p < 4; p++) {
            float4 v = stA[p];
            int row = a_row + p * 32;
            uint2 hi, lo;
            hi.x = packbf(v.x, v.y);
            hi.y = packbf(v.z, v.w);
            float rx = v.x - __bfloat162float(__float2bfloat16_rn(v.x));
            float ry = v.y - __bfloat162float(__float2bfloat16_rn(v.y));
            float rz = v.z - __bfloat162float(__float2bfloat16_rn(v.z));
            float rw = v.w - __bfloat162float(__float2bfloat16_rn(v.w));
            lo.x = packbf(rx, ry);
            lo.y = packbf(rz, rw);
            *(uint2*)&Ahi[row][a_c4] = hi;
            *(uint2*)&Alo[row][a_c4] = lo;
        }
        // ---- B: bf16 direct from L2-hot pre-split W ----
        #pragma unroll
        for (int p = 0; p < 2; p++) {
            int i  = tid + p * 256;
            int n  = i >> 2;
            int kg = (i & 3) << 3;
            uint4 h = *(const uint4*)&g_whi[(n0 + n) * CH + k0 + kg];
            uint4 l = *(const uint4*)&g_wlo[(n0 + n) * CH + k0 + kg];
            *(uint4*)&Bhi[n][kg] = h;
            *(uint4*)&Blo[n][kg] = l;
        }
        __syncthreads();

        // ---- prefetch next A chunk (overlaps MMA below) ----
        if (kc < 7) {
            #pragma unroll
            for (int p = 0; p < 4; p++) {
                int gr = bm + a_row + p * 32;
                stA[p] = (gr < N_NODES)
                    ? *(const float4*)&X[gr * CH + (k0 + TB_K) + a_c4]
                    : make_float4(0.f, 0.f, 0.f, 0.f);
            }
        }

        // ---- compute: 2 k-steps of 16 ----
        #pragma unroll
        for (int ks = 0; ks < 2; ks++) {
            const int kk = ks * 16;
            uint32_t ah[2][4], al[2][4];
            #pragma unroll
            for (int mi = 0; mi < 2; mi++) {
                int r0 = wm * 32 + mi * 16;
                ah[mi][0] = *(const uint32_t*)&Ahi[r0 + qr][kk + qc];
                ah[mi][1] = *(const uint32_t*)&Ahi[r0 + qr + 8][kk + qc];
                ah[mi][2] = *(const uint32_t*)&Ahi[r0 + qr][kk + qc + 8];
                ah[mi][3] = *(const uint32_t*)&Ahi[r0 + qr + 8][kk + qc + 8];
                al[mi][0] = *(const uint32_t*)&Alo[r0 + qr][kk + qc];
                al[mi][1] = *(const uint32_t*)&Alo[r0 + qr + 8][kk + qc];
                al[mi][2] = *(const uint32_t*)&Alo[r0 + qr][kk + qc + 8];
                al[mi][3] = *(const uint32_t*)&Alo[r0 + qr + 8][kk + qc + 8];
            }
            uint32_t bh[8][2], bl[8][2];
            #pragma unroll
            for (int ni = 0; ni < 8; ni++) {
                int n = wn * 64 + ni * 8 + qr;
                bh[ni][0] = *(const uint32_t*)&Bhi[n][kk + qc];
                bh[ni][1] = *(const uint32_t*)&Bhi[n][kk + qc + 8];
                bl[ni][0] = *(const uint32_t*)&Blo[n][kk + qc];
                bl[ni][1] = *(const uint32_t*)&Blo[n][kk + qc + 8];
            }
            #pragma unroll
            for (int mi = 0; mi < 2; mi++)
                #pragma unroll
                for (int ni = 0; ni < 8; ni++) {
                    mma16816(acc[mi][ni], ah[mi], bh[ni]);
                    mma16816(acc[mi][ni], ah[mi], bl[ni]);
                    mma16816(acc[mi][ni], al[mi], bh[ni]);
                }
        }
        __syncthreads();
    }

    // ---- epilogue: fp32 stores ----
    #pragma unroll
    for (int mi = 0; mi < 2; mi++) {
        int r0 = bm + wm * 32 + mi * 16 + qr;
        #pragma unroll
        for (int ni = 0; ni < 8; ni++) {
            int cg = n0 + wn * 64 + ni * 8 + qc;
            if (r0 < N_NODES)
                *(float2*)&g_xw[r0 * CH + cg] = make_float2(acc[mi][ni][0], acc[mi][ni][1]);
            if (r0 + 8 < N_NODES)
                *(float2*)&g_xw[(r0 + 8) * CH + cg] = make_float2(acc[mi][ni][2], acc[mi][ni][3]);
        }
    }
}

// ---------------- fused gather + self-loop + relu + node-sum ---------------------
// 2 warps per node (128 ch each, float4/lane). int2 metadata via uniform broadcast
// loads, double-buffered 8-edge batches for high MLP.
#define GATHER_BLOCKS 1184
__global__ void __launch_bounds__(256) k_gather(const float* __restrict__ conv_b) {
    const int lane = threadIdx.x & 31;
    const int warp = (blockIdx.x * blockDim.x + threadIdx.x) >> 5;
    const int nwarps = (GATHER_BLOCKS * 256) >> 5;
    const int half = warp & 1;
    const int c = (half << 7) + (lane << 2);

    const float4 b = *(const float4*)&conv_b[c];
    float hs0 = 0.f, hs1 = 0.f, hs2 = 0.f, hs3 = 0.f;

    for (int w = warp; w < 2 * N_NODES; w += nwarps) {
        const int n = w >> 1;
        float a0 = 0.f, a1 = 0.f, a2 = 0.f, a3 = 0.f;
        const int beg = g_rowptr[n];
        const int cnt = g_cnt[n];
        const int2* ec = g_csr + beg;
        const int nb = cnt >> 3;

        if (nb > 0) {
            int2 m0 = ec[0], m1 = ec[1], m2 = ec[2], m3 = ec[3],
                 m4 = ec[4], m5 = ec[5], m6 = ec[6], m7 = ec[7];
            for (int bi = 0; bi < nb; bi++) {
                int2 c0 = m0, c1 = m1, c2 = m2, c3 = m3,
                     c4 = m4, c5 = m5, c6 = m6, c7 = m7;
                if (bi + 1 < nb) {
                    const int2* nx = ec + (bi + 1) * 8;
                    m0 = nx[0]; m1 = nx[1]; m2 = nx[2]; m3 = nx[3];
                    m4 = nx[4]; m5 = nx[5]; m6 = nx[6]; m7 = nx[7];
                }
                #define GSTEP(e) { \
                    float4 v = *(const float4*)&g_xw[(e).x * CH + c]; \
                    float cf = __int_as_float((e).y); \
                    a0 += cf * v.x; a1 += cf * v.y; a2 += cf * v.z; a3 += cf * v.w; }
                GSTEP(c0) GSTEP(c1) GSTEP(c2) GSTEP(c3)
                GSTEP(c4) GSTEP(c5) GSTEP(c6) GSTEP(c7)
            }
        }
        for (int k = nb << 3; k < cnt; k++) {
            int2 e = ec[k];
            GSTEP(e)
        }
        #undef GSTEP
        {   // self loop: dinv[n]^2 * xw[n]
            float dn = g_dinv[n];
            float c2f = dn * dn;
            float4 v = *(const float4*)&g_xw[n * CH + c];
            a0 += c2f * v.x; a1 += c2f * v.y; a2 += c2f * v.z; a3 += c2f * v.w;
        }
        hs0 += fmaxf(a0 + b.x, 0.f);
        hs1 += fmaxf(a1 + b.y, 0.f);
        hs2 += fmaxf(a2 + b.z, 0.f);
        hs3 += fmaxf(a3 + b.w, 0.f);
    }
    atomicAdd(&g_s[c + 0], hs0);
    atomicAdd(&g_s[c + 1], hs1);
    atomicAdd(&g_s[c + 2], hs2);
    atomicAdd(&g_s[c + 3], hs3);
}

// ---------------- 4 tanh GEMVs -----------------------------------------------------
__global__ void k_gemv(const float* __restrict__ fc1w, const float* __restrict__ fc1b,
                       const float* __restrict__ fc2w, const float* __restrict__ fc2b,
                       const float* __restrict__ fc3w, const float* __restrict__ fc3b,
                       const float* __restrict__ fc4w, const float* __restrict__ fc4b,
                       float* __restrict__ out) {
    __shared__ float ss[CH];
    const int t = threadIdx.x;
    if (t < CH) ss[t] = g_s[t];
    __syncthreads();

    const float* w; const float* bb; int row;
    if (t < 256)      { w = fc1w; bb = fc1b; row = t; }
    else if (t < 512) { w = fc2w; bb = fc2b; row = t - 256; }
    else if (t < 640) { w = fc3w; bb = fc3b; row = t - 512; }
    else              { w = fc4w; bb = fc4b; row = t - 640; }

    float acc = bb[row];
    const float4* wr = (const float4*)(w + row * CH);
    #pragma unroll
    for (int k = 0; k < CH / 4; k++) {
        float4 wv = wr[k];
        acc += ss[4 * k + 0] * wv.x + ss[4 * k + 1] * wv.y +
               ss[4 * k + 2] * wv.z + ss[4 * k + 3] * wv.w;
    }
    out[t] = tanhf(acc);
}

// ---------------- launch -------------------------------------------------------------
extern "C" void kernel_launch(void* const* d_in, const int* in_sizes, int n_in,
                              void* d_out, int out_size) {
    const float* x      = (const float*)d_in[0];
    const int*   ei     = (const int*)  d_in[1];
    const float* conv_w = (const float*)d_in[2];
    const float* conv_b = (const float*)d_in[3];
    const float* fc1w   = (const float*)d_in[4];
    const float* fc1b   = (const float*)d_in[5];
    const float* fc2w   = (const float*)d_in[6];
    const float* fc2b   = (const float*)d_in[7];
    const float* fc3w   = (const float*)d_in[8];
    const float* fc3b   = (const float*)d_in[9];
    const float* fc4w   = (const float*)d_in[10];
    const float* fc4b   = (const float*)d_in[11];
    float* out = (float*)d_out;

    const int* src = ei;
    const int* dst = ei + N_EDGES;

    // launch order chosen so the GEMM is the 4th launch (ncu captures it)
    k_init0<<<NSCAN, 256>>>();                               // 1
    k_count<<<(N_EDGES + 255) / 256, 256>>>(src, dst);       // 2
    k_splitW<<<256, 256>>>(conv_w);                          // 3
    dim3 gg(CH / TB_N, (N_NODES + TB_M - 1) / TB_M);         // N fast, M slow
    k_gemm_mma<<<gg, 256>>>(x);                              // 4  <- profiled
    k_dinv<<<NSCAN, 256>>>();                                // 5
    k_scan1<<<NSCAN, 256>>>();                               // 6
    k_scan2<<<1, 256>>>();                                   // 7
    k_scan3<<<NSCAN, 256>>>();                               // 8
    k_fill<<<(N_EDGES + 255) / 256, 256>>>(src, dst);        // 9
    k_gather<<<GATHER_BLOCKS, 256>>>(conv_b);                // 10
    k_gemv<<<1, 768>>>(fc1w, fc1b, fc2w, fc2b, fc3w, fc3b, fc4w, fc4b, out); // 11
}

// round 8
// speedup vs baseline: 2.8572x; 1.3335x over previous
#include <cuda_runtime.h>
#include <cuda_bf16.h>
#include <cstdint>

#define N_NODES 50000
#define CH      256
#define N_EDGES 800000
#define NSCAN   196          // ceil(50000/256)

// ---------------- scratch (device globals) ------------------------------------
__device__ float g_xw  [N_NODES * CH];   // x @ conv_w fp32 (51.2 MB)
__device__ __nv_bfloat16 g_xhi[N_NODES * CH];  // X hi (25.6 MB)
__device__ __nv_bfloat16 g_xlo[N_NODES * CH];  // X lo (25.6 MB)
__device__ __nv_bfloat16 g_whi[CH * CH]; // W^T hi, [n][k]
__device__ __nv_bfloat16 g_wlo[CH * CH]; // W^T lo, [n][k]
__device__ float g_dinv[N_NODES];
__device__ int   g_sdeg[N_NODES];
__device__ int   g_cnt [N_NODES];
__device__ int   g_rowptr[N_NODES];
__device__ int   g_cursor[N_NODES];
__device__ int   g_bsum[NSCAN];
__device__ int2  g_csr[N_EDGES];         // {src, coef-as-int}
__device__ float g_s[CH];

__device__ __forceinline__ uint32_t packbf(float a, float b) {
    __nv_bfloat162 t = __floats2bfloat162_rn(a, b);
    return *(uint32_t*)&t;
}

// ---------------- prep: init counters + split/transpose W -----------------------
__global__ void k_prep(const float* __restrict__ W) {
    int i = blockIdx.x * blockDim.x + threadIdx.x;   // 0..65535
    if (i < N_NODES) { g_sdeg[i] = 1; g_cnt[i] = 0; }
    if (i < CH)      g_s[i] = 0.0f;
    int k = i >> 8, n = i & 255;
    float f = W[i];                                   // W[k][n]
    __nv_bfloat16 h = __float2bfloat16_rn(f);
    g_whi[n * CH + k] = h;
    g_wlo[n * CH + k] = __float2bfloat16_rn(f - __bfloat162float(h));
}

// ---------------- histograms -----------------------------------------------------
__global__ void k_count(const int* __restrict__ src, const int* __restrict__ dst) {
    int e = blockIdx.x * blockDim.x + threadIdx.x;
    if (e < N_EDGES) {
        atomicAdd(&g_sdeg[src[e]], 1);
        atomicAdd(&g_cnt[dst[e]], 1);
    }
}

// ---------------- X split: fp32 -> bf16 hi/lo ------------------------------------
__global__ void k_splitX(const float* __restrict__ X) {
    int i = blockIdx.x * blockDim.x + threadIdx.x;   // 0..3199999 (float4 units)
    float4 v = ((const float4*)X)[i];
    uint2 hi, lo;
    hi.x = packbf(v.x, v.y);
    hi.y = packbf(v.z, v.w);
    float rx = v.x - __bfloat162float(__float2bfloat16_rn(v.x));
    float ry = v.y - __bfloat162float(__float2bfloat16_rn(v.y));
    float rz = v.z - __bfloat162float(__float2bfloat16_rn(v.z));
    float rw = v.w - __bfloat162float(__float2bfloat16_rn(v.w));
    lo.x = packbf(rx, ry);
    lo.y = packbf(rz, rw);
    ((uint2*)g_xhi)[i] = hi;
    ((uint2*)g_xlo)[i] = lo;
}

// ---------------- 3-kernel exclusive scan over g_cnt ----------------------------
__global__ void k_scan1() {
    __shared__ int sh[256];
    int t = threadIdx.x, i = blockIdx.x * 256 + t;
    int v = (i < N_NODES) ? g_cnt[i] : 0;
    sh[t] = v; __syncthreads();
    #pragma unroll
    for (int off = 1; off < 256; off <<= 1) {
        int add = (t >= off) ? sh[t - off] : 0;
        __syncthreads();
        sh[t] += add;
        __syncthreads();
    }
    if (i < N_NODES) g_rowptr[i] = sh[t] - v;
    if (t == 255) g_bsum[blockIdx.x] = sh[255];
}

__global__ void k_scan2() {
    __shared__ int sh[256];
    int t = threadIdx.x;
    int v = (t < NSCAN) ? g_bsum[t] : 0;
    sh[t] = v; __syncthreads();
    #pragma unroll
    for (int off = 1; off < 256; off <<= 1) {
        int add = (t >= off) ? sh[t - off] : 0;
        __syncthreads();
        sh[t] += add;
        __syncthreads();
    }
    if (t < NSCAN) g_bsum[t] = sh[t] - v;
}

__global__ void k_scan3d() {
    int i = blockIdx.x * blockDim.x + threadIdx.x;
    if (i < N_NODES) {
        int r = g_rowptr[i] + g_bsum[i >> 8];
        g_rowptr[i] = r;
        g_cursor[i] = r;
        g_dinv[i] = rsqrtf((float)g_sdeg[i]);
    }
}

// ---------------- CSR fill (packed int2 metadata) --------------------------------
__global__ void k_fill(const int* __restrict__ src, const int* __restrict__ dst) {
    int e = blockIdx.x * blockDim.x + threadIdx.x;
    if (e < N_EDGES) {
        int s = src[e], d = dst[e];
        int pos = atomicAdd(&g_cursor[d], 1);
        float cf = g_dinv[s] * g_dinv[d];
        g_csr[pos] = make_int2(s, __float_as_int(cf));
    }
}

// =================================================================================
// Split-bf16 tensor-core GEMM, cp.async 2-stage pipeline, 2 CTAs/SM.
//   g_xw = X @ W;  D = Xhi*Whi + Xhi*Wlo + Xlo*Whi   (all operands pre-split bf16)
// CTA 128x128, 8 warps 4(M)x2(N), warp 32x64, K chunk 32 (8 chunks).
// =================================================================================
#define TB_M 128
#define TB_N 128
#define TB_K 32
#define ROWB 80            // bytes per SMEM row (40 bf16) -> conflict-free frags
#define OFF_AHI 0
#define OFF_ALO 10240
#define OFF_BHI 20480
#define OFF_BLO 30720
#define STAGE_BYTES 40960
#define GEMM_SMEM (2 * STAGE_BYTES)

__device__ __forceinline__ uint32_t smem_u32(const void* p) {
    uint32_t a;
    asm("{ .reg .u64 t; cvta.to.shared.u64 t, %1; cvt.u32.u64 %0, t; }"
        : "=r"(a) : "l"(p));
    return a;
}
#define CP16(dst, src) \
    asm volatile("cp.async.cg.shared.global [%0], [%1], 16;" :: "r"(dst), "l"(src))

__device__ __forceinline__ void mma16816(float* c, const uint32_t* a, const uint32_t* b) {
    asm volatile(
        "mma.sync.aligned.m16n8k16.row.col.f32.bf16.bf16.f32 "
        "{%0,%1,%2,%3}, {%4,%5,%6,%7}, {%8,%9}, {%0,%1,%2,%3};"
        : "+f"(c[0]), "+f"(c[1]), "+f"(c[2]), "+f"(c[3])
        : "r"(a[0]), "r"(a[1]), "r"(a[2]), "r"(a[3]), "r"(b[0]), "r"(b[1]));
}

__global__ void __launch_bounds__(256, 2) k_gemm_mma() {
    extern __shared__ char dsm[];
    const uint32_t sb = smem_u32(dsm);
    const int tid  = threadIdx.x;
    const int wid  = tid >> 5;
    const int lane = tid & 31;
    const int wm   = wid >> 1;
    const int wn   = wid & 1;
    const int bm   = blockIdx.y * TB_M;          // M slow
    const int n0   = blockIdx.x * TB_N;          // N fast -> X L2 reuse

    const int qr = lane >> 2;
    const int qc = (lane & 3) << 1;

    const int crow = tid >> 2;                   // 0..63 (+64)
    const int cseg = tid & 3;                    // 16B segment

    float acc[2][8][4];
    #pragma unroll
    for (int mi = 0; mi < 2; mi++)
        #pragma unroll
        for (int ni = 0; ni < 8; ni++)
            #pragma unroll
            for (int j = 0; j < 4; j++) acc[mi][ni][j] = 0.f;

    // ---- issue stage for chunk kc ----
    #define ISSUE(stage, kc) { \
        const int k0_ = (kc) * TB_K; \
        const uint32_t base_ = sb + (stage) * STAGE_BYTES; \
        _Pragma("unroll") \
        for (int p = 0; p < 2; p++) { \
            int row = crow + p * 64; \
            int gr = bm + row; if (gr > N_NODES - 1) gr = N_NODES - 1; \
            CP16(base_ + OFF_AHI + row * ROWB + cseg * 16, \
                 (const char*)(g_xhi + gr * CH + k0_ + cseg * 8)); \
            CP16(base_ + OFF_ALO + row * ROWB + cseg * 16, \
                 (const char*)(g_xlo + gr * CH + k0_ + cseg * 8)); \
            CP16(base_ + OFF_BHI + row * ROWB + cseg * 16, \
                 (const char*)(g_whi + (n0 + row) * CH + k0_ + cseg * 8)); \
            CP16(base_ + OFF_BLO + row * ROWB + cseg * 16, \
                 (const char*)(g_wlo + (n0 + row) * CH + k0_ + cseg * 8)); \
        } \
        asm volatile("cp.async.commit_group;"); }

    ISSUE(0, 0)

    for (int kc = 0; kc < 8; kc++) {
        const int cur = kc & 1;
        if (kc < 7) {
            ISSUE(cur ^ 1, kc + 1)
            asm volatile("cp.async.wait_group 1;");
        } else {
            asm volatile("cp.async.wait_group 0;");
        }
        __syncthreads();

        const __nv_bfloat16* Ah = (const __nv_bfloat16*)(dsm + cur * STAGE_BYTES + OFF_AHI);
        const __nv_bfloat16* Al = (const __nv_bfloat16*)(dsm + cur * STAGE_BYTES + OFF_ALO);
        const __nv_bfloat16* Bh = (const __nv_bfloat16*)(dsm + cur * STAGE_BYTES + OFF_BHI);
        const __nv_bfloat16* Bl = (const __nv_bfloat16*)(dsm + cur * STAGE_BYTES + OFF_BLO);

        #pragma unroll
        for (int ks = 0; ks < 2; ks++) {
            const int kk = ks * 16;
            uint32_t ah[2][4], al[2][4];
            #pragma unroll
            for (int mi = 0; mi < 2; mi++) {
                int r0 = wm * 32 + mi * 16;
                ah[mi][0] = *(const uint32_t*)&Ah[(r0 + qr) * 40 + kk + qc];
                ah[mi][1] = *(const uint32_t*)&Ah[(r0 + qr + 8) * 40 + kk + qc];
                ah[mi][2] = *(const uint32_t*)&Ah[(r0 + qr) * 40 + kk + qc + 8];
                ah[mi][3] = *(const uint32_t*)&Ah[(r0 + qr + 8) * 40 + kk + qc + 8];
                al[mi][0] = *(const uint32_t*)&Al[(r0 + qr) * 40 + kk + qc];
                al[mi][1] = *(const uint32_t*)&Al[(r0 + qr + 8) * 40 + kk + qc];
                al[mi][2] = *(const uint32_t*)&Al[(r0 + qr) * 40 + kk + qc + 8];
                al[mi][3] = *(const uint32_t*)&Al[(r0 + qr + 8) * 40 + kk + qc + 8];
            }
            uint32_t bh[8][2], bl[8][2];
            #pragma unroll
            for (int ni = 0; ni < 8; ni++) {
                int n = wn * 64 + ni * 8 + qr;
                bh[ni][0] = *(const uint32_t*)&Bh[n * 40 + kk + qc];
                bh[ni][1] = *(const uint32_t*)&Bh[n * 40 + kk + qc + 8];
                bl[ni][0] = *(const uint32_t*)&Bl[n * 40 + kk + qc];
                bl[ni][1] = *(const uint32_t*)&Bl[n * 40 + kk + qc + 8];
            }
            #pragma unroll
            for (int mi = 0; mi < 2; mi++)
                #pragma unroll
                for (int ni = 0; ni < 8; ni++) {
                    mma16816(acc[mi][ni], ah[mi], bh[ni]);
                    mma16816(acc[mi][ni], ah[mi], bl[ni]);
                    mma16816(acc[mi][ni], al[mi], bh[ni]);
                }
        }
        __syncthreads();
    }

    // ---- epilogue: fp32 stores ----
    #pragma unroll
    for (int mi = 0; mi < 2; mi++) {
        int r0 = bm + wm * 32 + mi * 16 + qr;
        #pragma unroll
        for (int ni = 0; ni < 8; ni++) {
            int cg = n0 + wn * 64 + ni * 8 + qc;
            if (r0 < N_NODES)
                *(float2*)&g_xw[r0 * CH + cg] = make_float2(acc[mi][ni][0], acc[mi][ni][1]);
            if (r0 + 8 < N_NODES)
                *(float2*)&g_xw[(r0 + 8) * CH + cg] = make_float2(acc[mi][ni][2], acc[mi][ni][3]);
        }
    }
}

// ---------------- fused gather + self-loop + relu + node-sum ---------------------
// One warp per node, 8 fp32 channels/lane (2 float4 per edge), double-buffered
// metadata, block-level SMEM reduction before global atomics.
#define GATHER_BLOCKS 1184
__global__ void __launch_bounds__(256) k_gather(const float* __restrict__ conv_b) {
    __shared__ float sacc[CH];
    const int tid  = threadIdx.x;
    const int lane = tid & 31;
    const int warp = (blockIdx.x * blockDim.x + tid) >> 5;
    const int nwarps = (GATHER_BLOCKS * 256) >> 5;
    const int c = lane << 3;

    sacc[tid] = 0.f;
    __syncthreads();

    const float4 b0 = *(const float4*)&conv_b[c];
    const float4 b1 = *(const float4*)&conv_b[c + 4];
    float hs[8] = {0.f,0.f,0.f,0.f,0.f,0.f,0.f,0.f};

    for (int n = warp; n < N_NODES; n += nwarps) {
        float a[8] = {0.f,0.f,0.f,0.f,0.f,0.f,0.f,0.f};
        const int beg = g_rowptr[n];
        const int cnt = g_cnt[n];
        const int2* ec = g_csr + beg;
        const int nb = cnt >> 3;

        #define GSTEP(e) { \
            const float* p = &g_xw[(e).x * CH + c]; \
            float4 v0 = *(const float4*)p; \
            float4 v1 = *(const float4*)(p + 4); \
            float cf = __int_as_float((e).y); \
            a[0] += cf * v0.x; a[1] += cf * v0.y; \
            a[2] += cf * v0.z; a[3] += cf * v0.w; \
            a[4] += cf * v1.x; a[5] += cf * v1.y; \
            a[6] += cf * v1.z; a[7] += cf * v1.w; }

        if (nb > 0) {
            int2 m0 = ec[0], m1 = ec[1], m2 = ec[2], m3 = ec[3],
                 m4 = ec[4], m5 = ec[5], m6 = ec[6], m7 = ec[7];
            for (int bi = 0; bi < nb; bi++) {
                int2 c0 = m0, c1 = m1, c2 = m2, c3 = m3,
                     c4 = m4, c5 = m5, c6 = m6, c7 = m7;
                if (bi + 1 < nb) {
                    const int2* nx = ec + (bi + 1) * 8;
                    m0 = nx[0]; m1 = nx[1]; m2 = nx[2]; m3 = nx[3];
                    m4 = nx[4]; m5 = nx[5]; m6 = nx[6]; m7 = nx[7];
                }
                GSTEP(c0) GSTEP(c1) GSTEP(c2) GSTEP(c3)
                GSTEP(c4) GSTEP(c5) GSTEP(c6) GSTEP(c7)
            }
        }
        for (int k = nb << 3; k < cnt; k++) {
            int2 e = ec[k];
            GSTEP(e)
        }
        #undef GSTEP
        {   // self loop: dinv[n]^2 * xw[n]
            float dn = g_dinv[n];
            float c2f = dn * dn;
            const float* p = &g_xw[n * CH + c];
            float4 v0 = *(const float4*)p;
            float4 v1 = *(const float4*)(p + 4);
            a[0] += c2f * v0.x; a[1] += c2f * v0.y;
            a[2] += c2f * v0.z; a[3] += c2f * v0.w;
            a[4] += c2f * v1.x; a[5] += c2f * v1.y;
            a[6] += c2f * v1.z; a[7] += c2f * v1.w;
        }
        hs[0] += fmaxf(a[0] + b0.x, 0.f);
        hs[1] += fmaxf(a[1] + b0.y, 0.f);
        hs[2] += fmaxf(a[2] + b0.z, 0.f);
        hs[3] += fmaxf(a[3] + b0.w, 0.f);
        hs[4] += fmaxf(a[4] + b1.x, 0.f);
        hs[5] += fmaxf(a[5] + b1.y, 0.f);
        hs[6] += fmaxf(a[6] + b1.z, 0.f);
        hs[7] += fmaxf(a[7] + b1.w, 0.f);
    }
    #pragma unroll
    for (int i = 0; i < 8; i++) atomicAdd(&sacc[c + i], hs[i]);
    __syncthreads();
    atomicAdd(&g_s[tid], sacc[tid]);
}

// ---------------- 4 tanh GEMVs -----------------------------------------------------
__global__ void k_gemv(const float* __restrict__ fc1w, const float* __restrict__ fc1b,
                       const float* __restrict__ fc2w, const float* __restrict__ fc2b,
                       const float* __restrict__ fc3w, const float* __restrict__ fc3b,
                       const float* __restrict__ fc4w, const float* __restrict__ fc4b,
                       float* __restrict__ out) {
    __shared__ float ss[CH];
    const int t = threadIdx.x;
    if (t < CH) ss[t] = g_s[t];
    __syncthreads();

    const float* w; const float* bb; int row;
    if (t < 256)      { w = fc1w; bb = fc1b; row = t; }
    else if (t < 512) { w = fc2w; bb = fc2b; row = t - 256; }
    else if (t < 640) { w = fc3w; bb = fc3b; row = t - 512; }
    else              { w = fc4w; bb = fc4b; row = t - 640; }

    float acc = bb[row];
    const float4* wr = (const float4*)(w + row * CH);
    #pragma unroll
    for (int k = 0; k < CH / 4; k++) {
        float4 wv = wr[k];
        acc += ss[4 * k + 0] * wv.x + ss[4 * k + 1] * wv.y +
               ss[4 * k + 2] * wv.z + ss[4 * k + 3] * wv.w;
    }
    out[t] = tanhf(acc);
}

// ---------------- launch -------------------------------------------------------------
extern "C" void kernel_launch(void* const* d_in, const int* in_sizes, int n_in,
                              void* d_out, int out_size) {
    const float* x      = (const float*)d_in[0];
    const int*   ei     = (const int*)  d_in[1];
    const float* conv_w = (const float*)d_in[2];
    const float* conv_b = (const float*)d_in[3];
    const float* fc1w   = (const float*)d_in[4];
    const float* fc1b   = (const float*)d_in[5];
    const float* fc2w   = (const float*)d_in[6];
    const float* fc2b   = (const float*)d_in[7];
    const float* fc3w   = (const float*)d_in[8];
    const float* fc3b   = (const float*)d_in[9];
    const float* fc4w   = (const float*)d_in[10];
    const float* fc4b   = (const float*)d_in[11];
    float* out = (float*)d_out;

    const int* src = ei;
    const int* dst = ei + N_EDGES;

    cudaFuncSetAttribute(k_gemm_mma, cudaFuncAttributeMaxDynamicSharedMemorySize,
                         GEMM_SMEM);

    k_prep<<<256, 256>>>(conv_w);                            // 1
    k_count<<<(N_EDGES + 255) / 256, 256>>>(src, dst);       // 2
    k_splitX<<<N_NODES * CH / 4 / 256, 256>>>(x);            // 3
    dim3 gg(CH / TB_N, (N_NODES + TB_M - 1) / TB_M);         // N fast, M slow
    k_gemm_mma<<<gg, 256, GEMM_SMEM>>>();                    // 4  <- profiled
    k_scan1<<<NSCAN, 256>>>();                               // 5
    k_scan2<<<1, 256>>>();                                   // 6
    k_scan3d<<<NSCAN, 256>>>();                              // 7
    k_fill<<<(N_EDGES + 255) / 256, 256>>>(src, dst);        // 8
    k_gather<<<GATHER_BLOCKS, 256>>>(conv_b);                // 9
    k_gemv<<<1, 768>>>(fc1w, fc1b, fc2w, fc2b, fc3w, fc3b, fc4w, fc4b, out); // 10
}

// round 9
// speedup vs baseline: 3.2579x; 1.1402x over previous
#include <cuda_runtime.h>
#include <cuda_bf16.h>
#include <cstdint>

#define N_NODES 50000
#define CH      256
#define N_EDGES 800000
#define NSCAN   196          // ceil(50000/256)

// ---------------- scratch (device globals) ------------------------------------
__device__ float g_xw [N_NODES * CH];    // x @ conv_w fp32 (51.2 MB)
__device__ float g_wt [CH * CH];         // W^T fp32, [n][k]
__device__ float g_dinv[N_NODES];
__device__ int   g_sdeg[N_NODES];
__device__ int   g_cnt [N_NODES];
__device__ int   g_rowptr[N_NODES];
__device__ int   g_cursor[N_NODES];
__device__ int   g_bsum[NSCAN];
__device__ int2  g_csr[N_EDGES];         // {src, coef-as-int}
__device__ float g_s[CH];

// ---------------- prep: init counters + transpose W ------------------------------
__global__ void k_prep(const float* __restrict__ W) {
    int i = blockIdx.x * blockDim.x + threadIdx.x;   // 0..65535
    if (i < N_NODES) { g_sdeg[i] = 1; g_cnt[i] = 0; }
    if (i < CH)      g_s[i] = 0.0f;
    int k = i >> 8, n = i & 255;
    g_wt[n * CH + k] = W[i];                          // W[k][n] -> WT[n][k]
}

// ---------------- histograms -----------------------------------------------------
__global__ void k_count(const int* __restrict__ src, const int* __restrict__ dst) {
    int e = blockIdx.x * blockDim.x + threadIdx.x;
    if (e < N_EDGES) {
        atomicAdd(&g_sdeg[src[e]], 1);
        atomicAdd(&g_cnt[dst[e]], 1);
    }
}

// ---------------- 3-kernel exclusive scan over g_cnt ----------------------------
__global__ void k_scan1() {
    __shared__ int sh[256];
    int t = threadIdx.x, i = blockIdx.x * 256 + t;
    int v = (i < N_NODES) ? g_cnt[i] : 0;
    sh[t] = v; __syncthreads();
    #pragma unroll
    for (int off = 1; off < 256; off <<= 1) {
        int add = (t >= off) ? sh[t - off] : 0;
        __syncthreads();
        sh[t] += add;
        __syncthreads();
    }
    if (i < N_NODES) g_rowptr[i] = sh[t] - v;
    if (t == 255) g_bsum[blockIdx.x] = sh[255];
}

__global__ void k_scan2() {
    __shared__ int sh[256];
    int t = threadIdx.x;
    int v = (t < NSCAN) ? g_bsum[t] : 0;
    sh[t] = v; __syncthreads();
    #pragma unroll
    for (int off = 1; off < 256; off <<= 1) {
        int add = (t >= off) ? sh[t - off] : 0;
        __syncthreads();
        sh[t] += add;
        __syncthreads();
    }
    if (t < NSCAN) g_bsum[t] = sh[t] - v;
}

__global__ void k_scan3d() {
    int i = blockIdx.x * blockDim.x + threadIdx.x;
    if (i < N_NODES) {
        int r = g_rowptr[i] + g_bsum[i >> 8];
        g_rowptr[i] = r;
        g_cursor[i] = r;
        g_dinv[i] = rsqrtf((float)g_sdeg[i]);
    }
}

// ---------------- CSR fill (packed int2 metadata) --------------------------------
__global__ void k_fill(const int* __restrict__ src, const int* __restrict__ dst) {
    int e = blockIdx.x * blockDim.x + threadIdx.x;
    if (e < N_EDGES) {
        int s = src[e], d = dst[e];
        int pos = atomicAdd(&g_cursor[d], 1);
        float cf = g_dinv[s] * g_dinv[d];
        g_csr[pos] = make_int2(s, __float_as_int(cf));
    }
}

// =================================================================================
// TF32 tensor-core GEMM, cp.async 2-stage pipeline, 2 CTAs/SM.
//   g_xw = X @ W   via m16n8k8 tf32 MMA, fp32 accumulate, RN tf32 conversion.
// CTA 128x128, 8 warps 4(M)x2(N), warp 32x64, K chunk 32 (8 chunks).
// SMEM rows padded to 36 floats (144B) -> conflict-free scalar fragment loads.
// =================================================================================
#define TB_M 128
#define TB_N 128
#define TB_K 32
#define AROW 36                 // floats per SMEM row
#define ROWB 144                // bytes per SMEM row
#define OFF_B 18432             // 128 * 144
#define STAGE_BYTES 36864
#define GEMM_SMEM (2 * STAGE_BYTES)

__device__ __forceinline__ uint32_t smem_u32(const void* p) {
    uint32_t a;
    asm("{ .reg .u64 t; cvta.to.shared.u64 t, %1; cvt.u32.u64 %0, t; }"
        : "=r"(a) : "l"(p));
    return a;
}
#define CP16(dst, src) \
    asm volatile("cp.async.cg.shared.global [%0], [%1], 16;" :: "r"(dst), "l"(src))

__device__ __forceinline__ uint32_t f2tf(float f) {
    uint32_t r;
    asm("cvt.rna.tf32.f32 %0, %1;" : "=r"(r) : "f"(f));
    return r;
}

__device__ __forceinline__ void mma_tf32(float* c, const uint32_t* a, const uint32_t* b) {
    asm volatile(
        "mma.sync.aligned.m16n8k8.row.col.f32.tf32.tf32.f32 "
        "{%0,%1,%2,%3}, {%4,%5,%6,%7}, {%8,%9}, {%0,%1,%2,%3};"
        : "+f"(c[0]), "+f"(c[1]), "+f"(c[2]), "+f"(c[3])
        : "r"(a[0]), "r"(a[1]), "r"(a[2]), "r"(a[3]), "r"(b[0]), "r"(b[1]));
}

__global__ void __launch_bounds__(256, 2) k_gemm_tf32(const float* __restrict__ X) {
    extern __shared__ char dsm[];
    const uint32_t sb = smem_u32(dsm);
    const int tid  = threadIdx.x;
    const int wid  = tid >> 5;
    const int lane = tid & 31;
    const int wm   = wid >> 1;
    const int wn   = wid & 1;
    const int bm   = blockIdx.y * TB_M;          // M slow
    const int n0   = blockIdx.x * TB_N;          // N fast -> X L2 reuse

    const int qr = lane >> 2;                    // 0..7
    const int qc = lane & 3;                     // 0..3

    float acc[2][8][4];
    #pragma unroll
    for (int mi = 0; mi < 2; mi++)
        #pragma unroll
        for (int ni = 0; ni < 8; ni++)
            #pragma unroll
            for (int j = 0; j < 4; j++) acc[mi][ni][j] = 0.f;

    // ---- issue stage for chunk kc: A rows (X) + B rows (WT), 16B segments ----
    #define ISSUE(stage, kc) { \
        const int k0_ = (kc) * TB_K; \
        const uint32_t base_ = sb + (stage) * STAGE_BYTES; \
        _Pragma("unroll") \
        for (int p = 0; p < 4; p++) { \
            int idx = tid + p * 256;            /* 0..1023 */ \
            int row = idx >> 3; \
            int seg = idx & 7; \
            int gr = bm + row; if (gr > N_NODES - 1) gr = N_NODES - 1; \
            CP16(base_ + row * ROWB + seg * 16, \
                 (const char*)(X + gr * CH + k0_ + seg * 4)); \
            CP16(base_ + OFF_B + row * ROWB + seg * 16, \
                 (const char*)(g_wt + (n0 + row) * CH + k0_ + seg * 4)); \
        } \
        asm volatile("cp.async.commit_group;"); }

    ISSUE(0, 0)

    for (int kc = 0; kc < 8; kc++) {
        const int cur = kc & 1;
        if (kc < 7) {
            ISSUE(cur ^ 1, kc + 1)
            asm volatile("cp.async.wait_group 1;");
        } else {
            asm volatile("cp.async.wait_group 0;");
        }
        __syncthreads();

        const float* As = (const float*)(dsm + cur * STAGE_BYTES);
        const float* Bs = (const float*)(dsm + cur * STAGE_BYTES + OFF_B);

        #pragma unroll
        for (int ks = 0; ks < 4; ks++) {          // 4 x k8
            const int kk = ks * 8;
            uint32_t a[2][4];
            #pragma unroll
            for (int mi = 0; mi < 2; mi++) {
                int r0 = wm * 32 + mi * 16;
                a[mi][0] = f2tf(As[(r0 + qr)     * AROW + kk + qc]);
                a[mi][1] = f2tf(As[(r0 + qr + 8) * AROW + kk + qc]);
                a[mi][2] = f2tf(As[(r0 + qr)     * AROW + kk + qc + 4]);
                a[mi][3] = f2tf(As[(r0 + qr + 8) * AROW + kk + qc + 4]);
            }
            uint32_t b[8][2];
            #pragma unroll
            for (int ni = 0; ni < 8; ni++) {
                int n = wn * 64 + ni * 8 + qr;
                b[ni][0] = f2tf(Bs[n * AROW + kk + qc]);
                b[ni][1] = f2tf(Bs[n * AROW + kk + qc + 4]);
            }
            #pragma unroll
            for (int mi = 0; mi < 2; mi++)
                #pragma unroll
                for (int ni = 0; ni < 8; ni++)
                    mma_tf32(acc[mi][ni], a[mi], b[ni]);
        }
        __syncthreads();
    }

    // ---- epilogue: fp32 stores (c cols = 2*qc, 2*qc+1) ----
    #pragma unroll
    for (int mi = 0; mi < 2; mi++) {
        int r0 = bm + wm * 32 + mi * 16 + qr;
        #pragma unroll
        for (int ni = 0; ni < 8; ni++) {
            int cg = n0 + wn * 64 + ni * 8 + qc * 2;
            if (r0 < N_NODES)
                *(float2*)&g_xw[r0 * CH + cg] = make_float2(acc[mi][ni][0], acc[mi][ni][1]);
            if (r0 + 8 < N_NODES)
                *(float2*)&g_xw[(r0 + 8) * CH + cg] = make_float2(acc[mi][ni][2], acc[mi][ni][3]);
        }
    }
}

// ---------------- fused gather + self-loop + relu + node-sum ---------------------
// One warp per node, 8 fp32 channels/lane (2 float4 per edge), double-buffered
// metadata, block-level SMEM reduction before global atomics.
#define GATHER_BLOCKS 1184
__global__ void __launch_bounds__(256) k_gather(const float* __restrict__ conv_b) {
    __shared__ float sacc[CH];
    const int tid  = threadIdx.x;
    const int lane = tid & 31;
    const int warp = (blockIdx.x * blockDim.x + tid) >> 5;
    const int nwarps = (GATHER_BLOCKS * 256) >> 5;
    const int c = lane << 3;

    sacc[tid] = 0.f;
    __syncthreads();

    const float4 b0 = *(const float4*)&conv_b[c];
    const float4 b1 = *(const float4*)&conv_b[c + 4];
    float hs[8] = {0.f,0.f,0.f,0.f,0.f,0.f,0.f,0.f};

    for (int n = warp; n < N_NODES; n += nwarps) {
        float a[8] = {0.f,0.f,0.f,0.f,0.f,0.f,0.f,0.f};
        const int beg = g_rowptr[n];
        const int cnt = g_cnt[n];
        const int2* ec = g_csr + beg;
        const int nb = cnt >> 3;

        #define GSTEP(e) { \
            const float* p = &g_xw[(e).x * CH + c]; \
            float4 v0 = *(const float4*)p; \
            float4 v1 = *(const float4*)(p + 4); \
            float cf = __int_as_float((e).y); \
            a[0] += cf * v0.x; a[1] += cf * v0.y; \
            a[2] += cf * v0.z; a[3] += cf * v0.w; \
            a[4] += cf * v1.x; a[5] += cf * v1.y; \
            a[6] += cf * v1.z; a[7] += cf * v1.w; }

        if (nb > 0) {
            int2 m0 = ec[0], m1 = ec[1], m2 = ec[2], m3 = ec[3],
                 m4 = ec[4], m5 = ec[5], m6 = ec[6], m7 = ec[7];
            for (int bi = 0; bi < nb; bi++) {
                int2 c0 = m0, c1 = m1, c2 = m2, c3 = m3,
                     c4 = m4, c5 = m5, c6 = m6, c7 = m7;
                if (bi + 1 < nb) {
                    const int2* nx = ec + (bi + 1) * 8;
                    m0 = nx[0]; m1 = nx[1]; m2 = nx[2]; m3 = nx[3];
                    m4 = nx[4]; m5 = nx[5]; m6 = nx[6]; m7 = nx[7];
                }
                GSTEP(c0) GSTEP(c1) GSTEP(c2) GSTEP(c3)
                GSTEP(c4) GSTEP(c5) GSTEP(c6) GSTEP(c7)
            }
        }
        for (int k = nb << 3; k < cnt; k++) {
            int2 e = ec[k];
            GSTEP(e)
        }
        #undef GSTEP
        {   // self loop: dinv[n]^2 * xw[n]
            float dn = g_dinv[n];
            float c2f = dn * dn;
            const float* p = &g_xw[n * CH + c];
            float4 v0 = *(const float4*)p;
            float4 v1 = *(const float4*)(p + 4);
            a[0] += c2f * v0.x; a[1] += c2f * v0.y;
            a[2] += c2f * v0.z; a[3] += c2f * v0.w;
            a[4] += c2f * v1.x; a[5] += c2f * v1.y;
            a[6] += c2f * v1.z; a[7] += c2f * v1.w;
        }
        hs[0] += fmaxf(a[0] + b0.x, 0.f);
        hs[1] += fmaxf(a[1] + b0.y, 0.f);
        hs[2] += fmaxf(a[2] + b0.z, 0.f);
        hs[3] += fmaxf(a[3] + b0.w, 0.f);
        hs[4] += fmaxf(a[4] + b1.x, 0.f);
        hs[5] += fmaxf(a[5] + b1.y, 0.f);
        hs[6] += fmaxf(a[6] + b1.z, 0.f);
        hs[7] += fmaxf(a[7] + b1.w, 0.f);
    }
    #pragma unroll
    for (int i = 0; i < 8; i++) atomicAdd(&sacc[c + i], hs[i]);
    __syncthreads();
    atomicAdd(&g_s[tid], sacc[tid]);
}

// ---------------- 4 tanh GEMVs -----------------------------------------------------
__global__ void k_gemv(const float* __restrict__ fc1w, const float* __restrict__ fc1b,
                       const float* __restrict__ fc2w, const float* __restrict__ fc2b,
                       const float* __restrict__ fc3w, const float* __restrict__ fc3b,
                       const float* __restrict__ fc4w, const float* __restrict__ fc4b,
                       float* __restrict__ out) {
    __shared__ float ss[CH];
    const int t = threadIdx.x;
    if (t < CH) ss[t] = g_s[t];
    __syncthreads();

    const float* w; const float* bb; int row;
    if (t < 256)      { w = fc1w; bb = fc1b; row = t; }
    else if (t < 512) { w = fc2w; bb = fc2b; row = t - 256; }
    else if (t < 640) { w = fc3w; bb = fc3b; row = t - 512; }
    else              { w = fc4w; bb = fc4b; row = t - 640; }

    float acc = bb[row];
    const float4* wr = (const float4*)(w + row * CH);
    #pragma unroll
    for (int k = 0; k < CH / 4; k++) {
        float4 wv = wr[k];
        acc += ss[4 * k + 0] * wv.x + ss[4 * k + 1] * wv.y +
               ss[4 * k + 2] * wv.z + ss[4 * k + 3] * wv.w;
    }
    out[t] = tanhf(acc);
}

// ---------------- launch -------------------------------------------------------------
extern "C" void kernel_launch(void* const* d_in, const int* in_sizes, int n_in,
                              void* d_out, int out_size) {
    const float* x      = (const float*)d_in[0];
    const int*   ei     = (const int*)  d_in[1];
    const float* conv_w = (const float*)d_in[2];
    const float* conv_b = (const float*)d_in[3];
    const float* fc1w   = (const float*)d_in[4];
    const float* fc1b   = (const float*)d_in[5];
    const float* fc2w   = (const float*)d_in[6];
    const float* fc2b   = (const float*)d_in[7];
    const float* fc3w   = (const float*)d_in[8];
    const float* fc3b   = (const float*)d_in[9];
    const float* fc4w   = (const float*)d_in[10];
    const float* fc4b   = (const float*)d_in[11];
    float* out = (float*)d_out;

    const int* src = ei;
    const int* dst = ei + N_EDGES;

    cudaFuncSetAttribute(k_gemm_tf32, cudaFuncAttributeMaxDynamicSharedMemorySize,
                         GEMM_SMEM);

    k_prep<<<256, 256>>>(conv_w);                            // 1
    k_count<<<(N_EDGES + 255) / 256, 256>>>(src, dst);       // 2
    k_scan1<<<NSCAN, 256>>>();                               // 3
    dim3 gg(CH / TB_N, (N_NODES + TB_M - 1) / TB_M);         // N fast, M slow
    k_gemm_tf32<<<gg, 256, GEMM_SMEM>>>(x);                  // 4  <- profiled
    k_scan2<<<1, 256>>>();                                   // 5
    k_scan3d<<<NSCAN, 256>>>();                              // 6
    k_fill<<<(N_EDGES + 255) / 256, 256>>>(src, dst);        // 7
    k_gather<<<GATHER_BLOCKS, 256>>>(conv_b);                // 8
    k_gemv<<<1, 768>>>(fc1w, fc1b, fc2w, fc2b, fc3w, fc3b, fc4w, fc4b, out); // 9
}